// round 1
// baseline (speedup 1.0000x reference)
#include <cuda_runtime.h>

#define NN 50000
#define NE 600000
#define NG 64
#define D  128
#define NCLS 10
#define AS_LD 68   // padded row for transposed A tile (k-major)

// ---------------- scratch (static device globals; no allocation) ------------
__device__ float g_edge[NE * D];        // updated edge features (307 MB)
__device__ float g_node[NN * D];        // updated node features
__device__ float g_NW[NN * 2 * D];      // per-node projections (NW1|NW2), also reused as NP
__device__ float g_ebar[NN * D];        // per-dst edge sums -> mean
__device__ float g_u[NG * D];
__device__ float g_uprojE[NG * D];      // u@We4 + We_b
__device__ float g_uprojN[NG * D];      // u@Wn3 + Wn_b
__device__ float g_gsum_node[NG * D];
__device__ float g_gsum_ebar[NG * D];
__device__ float g_indeg[NN];           // edges per dst node (pass-invariant)
__device__ float g_cntg[NG];            // nodes per graph  (pass-invariant)

// ---------------- init / bookkeeping ----------------------------------------
__global__ void k_init(const float* __restrict__ u_in)
{
    int i = blockIdx.x * blockDim.x + threadIdx.x;
    if (i < NN) g_indeg[i] = 0.f;
    if (i < NG) g_cntg[i] = 0.f;
    if (i < NG * D) g_u[i] = u_in[i];
}

__global__ void k_hist(const int* __restrict__ ei, const int* __restrict__ batch)
{
    int i = blockIdx.x * blockDim.x + threadIdx.x;
    if (i < NE) atomicAdd(&g_indeg[ei[NE + i]], 1.f);
    if (i < NN) atomicAdd(&g_cntg[batch[i]], 1.f);
}

__global__ void k_zero_pass()
{
    int i = blockIdx.x * blockDim.x + threadIdx.x;
    int stride = gridDim.x * blockDim.x;
    for (int x = i; x < NN * D; x += stride) g_ebar[x] = 0.f;
    if (i < NG * D) { g_gsum_node[i] = 0.f; g_gsum_ebar[i] = 0.f; }
}

// ---------------- tiny per-graph projections of u ---------------------------
__global__ void k_uproj(const float* __restrict__ We_w, const float* __restrict__ We_b,
                        const float* __restrict__ Wn_w, const float* __restrict__ Wn_b)
{
    int g = blockIdx.x, j = threadIdx.x;
    __shared__ float us[D];
    us[j] = g_u[g * D + j];
    __syncthreads();
    float aE = We_b[j], aN = Wn_b[j];
#pragma unroll 4
    for (int k = 0; k < D; k++) {
        float uv = us[k];
        aE = fmaf(uv, We_w[(3 * D + k) * D + j], aE);   // We4 rows 384..511
        aN = fmaf(uv, Wn_w[(2 * D + k) * D + j], aN);   // Wn3 rows 256..383
    }
    g_uprojE[g * D + j] = aE;
    g_uprojN[g * D + j] = aN;
}

// ---------------- generic 64x128x128 projection GEMM ------------------------
// C[row, coff + j] = sum_k A[row,k] * W[k,j];  W selected by blockIdx.y
__global__ void k_gemm_proj(const float* __restrict__ A,
                            const float* __restrict__ W0,
                            const float* __restrict__ W1,
                            float* __restrict__ C, int ldc, int M)
{
    extern __shared__ float sm[];
    float* As = sm;               // [D][AS_LD] (k-major transposed)
    float* Ws = sm + D * AS_LD;   // [D][D]
    const float* W = (blockIdx.y == 0) ? W0 : W1;
    int coff = blockIdx.y * D;
    int row0 = blockIdx.x * 64;
    int t = threadIdx.x;

    const float4* W4 = (const float4*)W;
    float4* Ws4 = (float4*)Ws;
#pragma unroll
    for (int i = 0; i < 32; i++) Ws4[t + i * 128] = W4[t + i * 128];
#pragma unroll
    for (int i = 0; i < 16; i++) {
        int idx = t + i * 128;
        int r = idx >> 5, kq = idx & 31;
        int row = row0 + r; if (row >= M) row = M - 1;
        float4 v = *(const float4*)(A + (size_t)row * D + kq * 4);
        As[(kq * 4 + 0) * AS_LD + r] = v.x;
        As[(kq * 4 + 1) * AS_LD + r] = v.y;
        As[(kq * 4 + 2) * AS_LD + r] = v.z;
        As[(kq * 4 + 3) * AS_LD + r] = v.w;
    }
    __syncthreads();

    int j0 = (t & 15) * 8, r0 = (t >> 4) * 8;
    float acc[8][8];
#pragma unroll
    for (int a = 0; a < 8; a++)
#pragma unroll
        for (int b = 0; b < 8; b++) acc[a][b] = 0.f;

#pragma unroll 4
    for (int k = 0; k < D; k++) {
        float a[8], b[8];
        *(float4*)&a[0] = *(float4*)&As[k * AS_LD + r0];
        *(float4*)&a[4] = *(float4*)&As[k * AS_LD + r0 + 4];
        *(float4*)&b[0] = *(float4*)&Ws[k * D + j0];
        *(float4*)&b[4] = *(float4*)&Ws[k * D + j0 + 4];
#pragma unroll
        for (int rr = 0; rr < 8; rr++)
#pragma unroll
            for (int jj = 0; jj < 8; jj++)
                acc[rr][jj] = fmaf(a[rr], b[jj], acc[rr][jj]);
    }

#pragma unroll
    for (int rr = 0; rr < 8; rr++) {
        int row = row0 + r0 + rr;
        if (row < M) {
            *(float4*)(C + (size_t)row * ldc + coff + j0) =
                make_float4(acc[rr][0], acc[rr][1], acc[rr][2], acc[rr][3]);
            *(float4*)(C + (size_t)row * ldc + coff + j0 + 4) =
                make_float4(acc[rr][4], acc[rr][5], acc[rr][6], acc[rr][7]);
        }
    }
}

// ---------------- edge update: relu(NW1[src]+NW2[dst]+uprojE[g] + e@We3) ----
// epilogue: store new edge feature + RED into per-dst sums
__global__ void k_edge(const float* __restrict__ Eattr,
                       const float* __restrict__ We_w,
                       const int* __restrict__ ei,
                       const int* __restrict__ batch)
{
    extern __shared__ float sm[];
    float* As = sm;
    float* Ws = sm + D * AS_LD;
    int* src_s = (int*)(Ws + D * D);
    int* dst_s = src_s + 64;
    int* grp_s = dst_s + 64;

    int e0 = blockIdx.x * 64;
    int t = threadIdx.x;
    if (t < 64) {
        int s = ei[e0 + t];
        int d = ei[NE + e0 + t];
        src_s[t] = s; dst_s[t] = d; grp_s[t] = batch[s];
    }
    const float4* W4 = (const float4*)(We_w + 2 * D * D);  // We3 rows 256..383
    float4* Ws4 = (float4*)Ws;
#pragma unroll
    for (int i = 0; i < 32; i++) Ws4[t + i * 128] = W4[t + i * 128];
#pragma unroll
    for (int i = 0; i < 16; i++) {
        int idx = t + i * 128;
        int r = idx >> 5, kq = idx & 31;
        float4 v = *(const float4*)(Eattr + (size_t)(e0 + r) * D + kq * 4);
        As[(kq * 4 + 0) * AS_LD + r] = v.x;
        As[(kq * 4 + 1) * AS_LD + r] = v.y;
        As[(kq * 4 + 2) * AS_LD + r] = v.z;
        As[(kq * 4 + 3) * AS_LD + r] = v.w;
    }
    __syncthreads();

    int j0 = (t & 15) * 8, r0 = (t >> 4) * 8;
    float acc[8][8];
#pragma unroll
    for (int rr = 0; rr < 8; rr++) {
        int r = r0 + rr;
        int s = src_s[r], d = dst_s[r], g = grp_s[r];
        const float* ps = g_NW + (size_t)s * 2 * D + j0;
        const float* pd = g_NW + (size_t)d * 2 * D + D + j0;
        const float* pu = g_uprojE + (size_t)g * D + j0;
        float4 s0 = *(const float4*)ps,       s1 = *(const float4*)(ps + 4);
        float4 d0 = *(const float4*)pd,       d1 = *(const float4*)(pd + 4);
        float4 u0 = *(const float4*)pu,       u1 = *(const float4*)(pu + 4);
        acc[rr][0] = s0.x + d0.x + u0.x;  acc[rr][1] = s0.y + d0.y + u0.y;
        acc[rr][2] = s0.z + d0.z + u0.z;  acc[rr][3] = s0.w + d0.w + u0.w;
        acc[rr][4] = s1.x + d1.x + u1.x;  acc[rr][5] = s1.y + d1.y + u1.y;
        acc[rr][6] = s1.z + d1.z + u1.z;  acc[rr][7] = s1.w + d1.w + u1.w;
    }

#pragma unroll 4
    for (int k = 0; k < D; k++) {
        float a[8], b[8];
        *(float4*)&a[0] = *(float4*)&As[k * AS_LD + r0];
        *(float4*)&a[4] = *(float4*)&As[k * AS_LD + r0 + 4];
        *(float4*)&b[0] = *(float4*)&Ws[k * D + j0];
        *(float4*)&b[4] = *(float4*)&Ws[k * D + j0 + 4];
#pragma unroll
        for (int rr = 0; rr < 8; rr++)
#pragma unroll
            for (int jj = 0; jj < 8; jj++)
                acc[rr][jj] = fmaf(a[rr], b[jj], acc[rr][jj]);
    }

#pragma unroll
    for (int rr = 0; rr < 8; rr++) {
        int r = r0 + rr;
        int e = e0 + r;
        int d = dst_s[r];
        float y[8];
#pragma unroll
        for (int jj = 0; jj < 8; jj++) y[jj] = fmaxf(acc[rr][jj], 0.f);
        *(float4*)(g_edge + (size_t)e * D + j0)     = make_float4(y[0], y[1], y[2], y[3]);
        *(float4*)(g_edge + (size_t)e * D + j0 + 4) = make_float4(y[4], y[5], y[6], y[7]);
        float* pb = g_ebar + (size_t)d * D + j0;
#pragma unroll
        for (int jj = 0; jj < 8; jj++) atomicAdd(pb + jj, y[jj]);
    }
}

// ---------------- node update: relu(NP + ebar@Wn2 + uprojN[batch]) ----------
// also accumulates per-graph sums of ebar (normalized) and new node features
__global__ void k_node(const int* __restrict__ batch,
                       const float* __restrict__ Wn_w)
{
    extern __shared__ float sm[];
    float* As = sm;
    float* Ws = sm + D * AS_LD;
    float* inv_s = Ws + D * D;
    int* b_s = (int*)(inv_s + 64);

    int row0 = blockIdx.x * 64;
    int t = threadIdx.x;
    if (t < 64) {
        int row = row0 + t;
        if (row < NN) { inv_s[t] = 1.f / fmaxf(g_indeg[row], 1.f); b_s[t] = batch[row]; }
        else          { inv_s[t] = 0.f; b_s[t] = 0; }
    }
    __syncthreads();

    const float4* W4 = (const float4*)(Wn_w + D * D);   // Wn2 rows 128..255
    float4* Ws4 = (float4*)Ws;
#pragma unroll
    for (int i = 0; i < 32; i++) Ws4[t + i * 128] = W4[t + i * 128];
#pragma unroll
    for (int i = 0; i < 16; i++) {
        int idx = t + i * 128;
        int r = idx >> 5, kq = idx & 31;
        int row = row0 + r;
        float4 v = make_float4(0.f, 0.f, 0.f, 0.f);
        if (row < NN) {
            v = *(const float4*)(g_ebar + (size_t)row * D + kq * 4);
            float sc = inv_s[r];
            v.x *= sc; v.y *= sc; v.z *= sc; v.w *= sc;
            float* pg = g_gsum_ebar + (size_t)b_s[r] * D + kq * 4;
            atomicAdd(pg + 0, v.x); atomicAdd(pg + 1, v.y);
            atomicAdd(pg + 2, v.z); atomicAdd(pg + 3, v.w);
        }
        As[(kq * 4 + 0) * AS_LD + r] = v.x;
        As[(kq * 4 + 1) * AS_LD + r] = v.y;
        As[(kq * 4 + 2) * AS_LD + r] = v.z;
        As[(kq * 4 + 3) * AS_LD + r] = v.w;
    }
    __syncthreads();

    int j0 = (t & 15) * 8, r0 = (t >> 4) * 8;
    float acc[8][8];
#pragma unroll
    for (int rr = 0; rr < 8; rr++) {
        int r = r0 + rr, row = row0 + r;
        int rc = (row < NN) ? row : NN - 1;
        const float* pp = g_NW + (size_t)rc * 2 * D + j0;   // NP = node@Wn1
        const float* pu = g_uprojN + (size_t)b_s[r] * D + j0;
        float4 p0 = *(const float4*)pp, p1 = *(const float4*)(pp + 4);
        float4 u0 = *(const float4*)pu, u1 = *(const float4*)(pu + 4);
        acc[rr][0] = p0.x + u0.x;  acc[rr][1] = p0.y + u0.y;
        acc[rr][2] = p0.z + u0.z;  acc[rr][3] = p0.w + u0.w;
        acc[rr][4] = p1.x + u1.x;  acc[rr][5] = p1.y + u1.y;
        acc[rr][6] = p1.z + u1.z;  acc[rr][7] = p1.w + u1.w;
    }

#pragma unroll 4
    for (int k = 0; k < D; k++) {
        float a[8], b[8];
        *(float4*)&a[0] = *(float4*)&As[k * AS_LD + r0];
        *(float4*)&a[4] = *(float4*)&As[k * AS_LD + r0 + 4];
        *(float4*)&b[0] = *(float4*)&Ws[k * D + j0];
        *(float4*)&b[4] = *(float4*)&Ws[k * D + j0 + 4];
#pragma unroll
        for (int rr = 0; rr < 8; rr++)
#pragma unroll
            for (int jj = 0; jj < 8; jj++)
                acc[rr][jj] = fmaf(a[rr], b[jj], acc[rr][jj]);
    }

#pragma unroll
    for (int rr = 0; rr < 8; rr++) {
        int row = row0 + r0 + rr;
        if (row < NN) {
            int gb = b_s[r0 + rr];
            float y[8];
#pragma unroll
            for (int jj = 0; jj < 8; jj++) y[jj] = fmaxf(acc[rr][jj], 0.f);
            *(float4*)(g_node + (size_t)row * D + j0)     = make_float4(y[0], y[1], y[2], y[3]);
            *(float4*)(g_node + (size_t)row * D + j0 + 4) = make_float4(y[4], y[5], y[6], y[7]);
            float* pg = g_gsum_node + (size_t)gb * D + j0;
#pragma unroll
            for (int jj = 0; jj < 8; jj++) atomicAdd(pg + jj, y[jj]);
        }
    }
}

// ---------------- global update ----------------------------------------------
__global__ void k_global(const float* __restrict__ Wg_w, const float* __restrict__ Wg_b)
{
    int g = blockIdx.x, j = threadIdx.x;
    __shared__ float nm[D], em[D], uu[D];
    float inv = 1.f / fmaxf(g_cntg[g], 1.f);
    nm[j] = g_gsum_node[g * D + j] * inv;
    em[j] = g_gsum_ebar[g * D + j] * inv;
    uu[j] = g_u[g * D + j];
    __syncthreads();
    float acc = Wg_b[j];
#pragma unroll 4
    for (int k = 0; k < D; k++) {
        acc = fmaf(nm[k], Wg_w[k * D + j], acc);
        acc = fmaf(em[k], Wg_w[(D + k) * D + j], acc);
        acc = fmaf(uu[k], Wg_w[(2 * D + k) * D + j], acc);
    }
    g_u[g * D + j] = fmaxf(acc, 0.f);
}

// ---------------- readout ----------------------------------------------------
__global__ void k_readout(const float* __restrict__ lin_w, const float* __restrict__ lin_b,
                          float* __restrict__ out)
{
    int g = blockIdx.x, t = threadIdx.x;
    __shared__ float pooled[3 * D];
    float inv = 1.f / fmaxf(g_cntg[g], 1.f);
    pooled[t]         = g_gsum_node[g * D + t] * inv;
    pooled[D + t]     = g_gsum_ebar[g * D + t] * inv;
    pooled[2 * D + t] = g_u[g * D + t];
    __syncthreads();
    if (t < NCLS) {
        float acc = lin_b[t];
#pragma unroll 4
        for (int k = 0; k < 3 * D; k++) acc = fmaf(pooled[k], lin_w[k * NCLS + t], acc);
        out[g * NCLS + t] = acc;
    }
}

// ---------------- host launcher ----------------------------------------------
extern "C" void kernel_launch(void* const* d_in, const int* in_sizes, int n_in,
                              void* d_out, int out_size)
{
    const float* node_in = (const float*)d_in[0];
    const float* edge_in = (const float*)d_in[1];
    const float* u_in    = (const float*)d_in[2];
    const int*   ei      = (const int*)d_in[3];
    const int*   batch   = (const int*)d_in[4];
    const float* We_w = (const float*)d_in[5];
    const float* We_b = (const float*)d_in[6];
    const float* Wn_w = (const float*)d_in[7];
    const float* Wn_b = (const float*)d_in[8];
    const float* Wg_w = (const float*)d_in[9];
    const float* Wg_b = (const float*)d_in[10];
    const float* lin_w = (const float*)d_in[11];
    const float* lin_b = (const float*)d_in[12];
    float* out = (float*)d_out;

    float *p_NW = nullptr, *p_node = nullptr, *p_edge = nullptr;
    cudaGetSymbolAddress((void**)&p_NW,   g_NW);
    cudaGetSymbolAddress((void**)&p_node, g_node);
    cudaGetSymbolAddress((void**)&p_edge, g_edge);

    const int SMEM_GEMM = (D * AS_LD + D * D) * 4;
    const int SMEM_EDGE = SMEM_GEMM + 3 * 64 * 4;
    const int SMEM_NODE = SMEM_GEMM + 2 * 64 * 4;
    cudaFuncSetAttribute(k_gemm_proj, cudaFuncAttributeMaxDynamicSharedMemorySize, SMEM_GEMM);
    cudaFuncSetAttribute(k_edge,      cudaFuncAttributeMaxDynamicSharedMemorySize, SMEM_EDGE);
    cudaFuncSetAttribute(k_node,      cudaFuncAttributeMaxDynamicSharedMemorySize, SMEM_NODE);

    k_init<<<(NN + 255) / 256, 256>>>(u_in);
    k_hist<<<(NE + 255) / 256, 256>>>(ei, batch);

    const float* nsrc = node_in;
    const float* esrc = edge_in;
    int nrb = (NN + 63) / 64;
    for (int p = 0; p < 3; p++) {
        k_zero_pass<<<1024, 256>>>();
        k_uproj<<<NG, D>>>(We_w, We_b, Wn_w, Wn_b);
        // NW1|NW2 = node @ [We1|We2]
        k_gemm_proj<<<dim3(nrb, 2), 128, SMEM_GEMM>>>(nsrc, We_w, We_w + D * D, p_NW, 2 * D, NN);
        // edge update + scatter into per-dst sums
        k_edge<<<NE / 64, 128, SMEM_EDGE>>>(esrc, We_w, ei, batch);
        // NP = node @ Wn1 (reuses g_NW first half)
        k_gemm_proj<<<dim3(nrb, 1), 128, SMEM_GEMM>>>(nsrc, Wn_w, Wn_w, p_NW, 2 * D, NN);
        // node update + per-graph sums
        k_node<<<nrb, 128, SMEM_NODE>>>(batch, Wn_w);
        // global update
        k_global<<<NG, D>>>(Wg_w, Wg_b);
        nsrc = p_node;
        esrc = p_edge;
    }
    k_readout<<<NG, D>>>(lin_w, lin_b, out);
}

// round 2
// speedup vs baseline: 1.3822x; 1.3822x over previous
#include <cuda_runtime.h>

#define NN 50000
#define NE 600000
#define NG 64
#define D  128
#define NCLS 10
#define AS_LD 68   // padded row for transposed A tile (k-major)

// ---------------- scratch (static device globals; no allocation) ------------
__device__ float g_edge[NE * D];        // updated edge features (307 MB)
__device__ float g_node[NN * D];        // updated node features
__device__ float g_NW[NN * 2 * D];      // per-node projections (NW1|NW2)
__device__ float g_ebar[NN * D];        // per-dst edge sums -> mean
__device__ float g_u[NG * D];
__device__ float g_uprojE[NG * D];      // u@We4 + We_b
__device__ float g_uprojN[NG * D];      // u@Wn3 + Wn_b
__device__ float g_gsum_node[NG * D];
__device__ float g_gsum_ebar[NG * D];
__device__ float g_indeg[NN];           // edges per dst node (pass-invariant)
__device__ float g_cntg[NG];            // nodes per graph  (pass-invariant)

// ---------------- packed fp32x2 helpers --------------------------------------
__device__ __forceinline__ unsigned long long pack2(float lo, float hi) {
    unsigned long long r;
    asm("mov.b64 %0, {%1, %2};" : "=l"(r) : "f"(lo), "f"(hi));
    return r;
}
__device__ __forceinline__ unsigned long long pack2s(float v) {
    unsigned long long r;
    asm("mov.b64 %0, {%1, %1};" : "=l"(r) : "f"(v));
    return r;
}
__device__ __forceinline__ float2 unpack2(unsigned long long p) {
    float2 v;
    asm("mov.b64 {%0, %1}, %2;" : "=f"(v.x), "=f"(v.y) : "l"(p));
    return v;
}
__device__ __forceinline__ void red_add_v4(float* p, float a, float b, float c, float d) {
    asm volatile("red.global.add.v4.f32 [%0], {%1,%2,%3,%4};"
                 :: "l"(p), "f"(a), "f"(b), "f"(c), "f"(d) : "memory");
}

// 64x128x128 micro-kernel mainloop with packed FFMA2.
// accp[rr][jp] accumulates output pair (j0+2jp, j0+2jp+1) for row r0+rr.
__device__ __forceinline__ void mm_accum(const float* __restrict__ As,
                                         const float* __restrict__ Ws,
                                         int r0, int j0,
                                         unsigned long long accp[8][4])
{
#pragma unroll 4
    for (int k = 0; k < D; k++) {
        float a[8];
        *(float4*)&a[0] = *(const float4*)&As[k * AS_LD + r0];
        *(float4*)&a[4] = *(const float4*)&As[k * AS_LD + r0 + 4];
        unsigned long long bp[4];
        const unsigned long long* wp = (const unsigned long long*)&Ws[k * D + j0];
        bp[0] = wp[0]; bp[1] = wp[1]; bp[2] = wp[2]; bp[3] = wp[3];
#pragma unroll
        for (int rr = 0; rr < 8; rr++) {
            unsigned long long ap = pack2s(a[rr]);
#pragma unroll
            for (int jp = 0; jp < 4; jp++)
                asm("fma.rn.f32x2 %0, %1, %2, %0;"
                    : "+l"(accp[rr][jp]) : "l"(ap), "l"(bp[jp]));
        }
    }
}

// ---------------- init / bookkeeping ----------------------------------------
__global__ void k_init(const float* __restrict__ u_in)
{
    int i = blockIdx.x * blockDim.x + threadIdx.x;
    if (i < NN) g_indeg[i] = 0.f;
    if (i < NG) g_cntg[i] = 0.f;
    if (i < NG * D) g_u[i] = u_in[i];
}

__global__ void k_hist(const int* __restrict__ ei, const int* __restrict__ batch)
{
    int i = blockIdx.x * blockDim.x + threadIdx.x;
    if (i < NE) atomicAdd(&g_indeg[ei[NE + i]], 1.f);
    if (i < NN) atomicAdd(&g_cntg[batch[i]], 1.f);
}

__global__ void k_zero_pass()
{
    int i = blockIdx.x * blockDim.x + threadIdx.x;
    int stride = gridDim.x * blockDim.x;
    for (int x = i; x < NN * D; x += stride) g_ebar[x] = 0.f;
    if (i < NG * D) { g_gsum_node[i] = 0.f; g_gsum_ebar[i] = 0.f; }
}

// ---------------- initial per-graph projections of u (pass 0 only) ----------
__global__ void k_uproj(const float* __restrict__ We_w, const float* __restrict__ We_b,
                        const float* __restrict__ Wn_w, const float* __restrict__ Wn_b)
{
    int g = blockIdx.x, j = threadIdx.x;
    __shared__ float us[D];
    us[j] = g_u[g * D + j];
    __syncthreads();
    float aE = We_b[j], aN = Wn_b[j];
#pragma unroll 4
    for (int k = 0; k < D; k++) {
        float uv = us[k];
        aE = fmaf(uv, We_w[(3 * D + k) * D + j], aE);   // We4 rows 384..511
        aN = fmaf(uv, Wn_w[(2 * D + k) * D + j], aN);   // Wn3 rows 256..383
    }
    g_uprojE[g * D + j] = aE;
    g_uprojN[g * D + j] = aN;
}

// ---------------- generic 64x128x128 projection GEMM ------------------------
__global__ void k_gemm_proj(const float* __restrict__ A,
                            const float* __restrict__ W0,
                            const float* __restrict__ W1,
                            float* __restrict__ C, int ldc, int M)
{
    extern __shared__ float sm[];
    float* As = sm;               // [D][AS_LD] (k-major transposed)
    float* Ws = sm + D * AS_LD;   // [D][D]
    const float* W = (blockIdx.y == 0) ? W0 : W1;
    int coff = blockIdx.y * D;
    int row0 = blockIdx.x * 64;
    int t = threadIdx.x;

    const float4* W4 = (const float4*)W;
    float4* Ws4 = (float4*)Ws;
#pragma unroll
    for (int i = 0; i < 32; i++) Ws4[t + i * 128] = W4[t + i * 128];
#pragma unroll
    for (int i = 0; i < 16; i++) {
        int idx = t + i * 128;
        int r = idx >> 5, kq = idx & 31;
        int row = row0 + r; if (row >= M) row = M - 1;
        float4 v = *(const float4*)(A + (size_t)row * D + kq * 4);
        As[(kq * 4 + 0) * AS_LD + r] = v.x;
        As[(kq * 4 + 1) * AS_LD + r] = v.y;
        As[(kq * 4 + 2) * AS_LD + r] = v.z;
        As[(kq * 4 + 3) * AS_LD + r] = v.w;
    }
    __syncthreads();

    int j0 = (t & 15) * 8, r0 = (t >> 4) * 8;
    unsigned long long accp[8][4];
#pragma unroll
    for (int a = 0; a < 8; a++)
#pragma unroll
        for (int b = 0; b < 4; b++) accp[a][b] = 0ULL;

    mm_accum(As, Ws, r0, j0, accp);

#pragma unroll
    for (int rr = 0; rr < 8; rr++) {
        int row = row0 + r0 + rr;
        if (row < M) {
            float2 v0 = unpack2(accp[rr][0]), v1 = unpack2(accp[rr][1]);
            float2 v2 = unpack2(accp[rr][2]), v3 = unpack2(accp[rr][3]);
            *(float4*)(C + (size_t)row * ldc + coff + j0)     = make_float4(v0.x, v0.y, v1.x, v1.y);
            *(float4*)(C + (size_t)row * ldc + coff + j0 + 4) = make_float4(v2.x, v2.y, v3.x, v3.y);
        }
    }
}

// ---------------- edge update: relu(NW1[src]+NW2[dst]+uprojE[g] + e@We3) ----
__global__ void k_edge(const float* __restrict__ Eattr,
                       const float* __restrict__ We_w,
                       const int* __restrict__ ei,
                       const int* __restrict__ batch)
{
    extern __shared__ float sm[];
    float* As = sm;
    float* Ws = sm + D * AS_LD;
    int* src_s = (int*)(Ws + D * D);
    int* dst_s = src_s + 64;
    int* grp_s = dst_s + 64;

    int e0 = blockIdx.x * 64;
    int t = threadIdx.x;
    if (t < 64) {
        int s = ei[e0 + t];
        int d = ei[NE + e0 + t];
        src_s[t] = s; dst_s[t] = d; grp_s[t] = batch[s];
    }
    const float4* W4 = (const float4*)(We_w + 2 * D * D);  // We3 rows 256..383
    float4* Ws4 = (float4*)Ws;
#pragma unroll
    for (int i = 0; i < 32; i++) Ws4[t + i * 128] = W4[t + i * 128];
#pragma unroll
    for (int i = 0; i < 16; i++) {
        int idx = t + i * 128;
        int r = idx >> 5, kq = idx & 31;
        float4 v = *(const float4*)(Eattr + (size_t)(e0 + r) * D + kq * 4);
        As[(kq * 4 + 0) * AS_LD + r] = v.x;
        As[(kq * 4 + 1) * AS_LD + r] = v.y;
        As[(kq * 4 + 2) * AS_LD + r] = v.z;
        As[(kq * 4 + 3) * AS_LD + r] = v.w;
    }
    __syncthreads();

    int j0 = (t & 15) * 8, r0 = (t >> 4) * 8;
    unsigned long long accp[8][4];
#pragma unroll
    for (int rr = 0; rr < 8; rr++) {
        int r = r0 + rr;
        int s = src_s[r], d = dst_s[r], g = grp_s[r];
        const float* ps = g_NW + (size_t)s * 2 * D + j0;
        const float* pd = g_NW + (size_t)d * 2 * D + D + j0;
        const float* pu = g_uprojE + (size_t)g * D + j0;
        float4 s0 = *(const float4*)ps,  s1 = *(const float4*)(ps + 4);
        float4 d0 = *(const float4*)pd,  d1 = *(const float4*)(pd + 4);
        float4 u0 = *(const float4*)pu,  u1 = *(const float4*)(pu + 4);
        accp[rr][0] = pack2(s0.x + d0.x + u0.x, s0.y + d0.y + u0.y);
        accp[rr][1] = pack2(s0.z + d0.z + u0.z, s0.w + d0.w + u0.w);
        accp[rr][2] = pack2(s1.x + d1.x + u1.x, s1.y + d1.y + u1.y);
        accp[rr][3] = pack2(s1.z + d1.z + u1.z, s1.w + d1.w + u1.w);
    }

    mm_accum(As, Ws, r0, j0, accp);

#pragma unroll
    for (int rr = 0; rr < 8; rr++) {
        int r = r0 + rr;
        int e = e0 + r;
        int d = dst_s[r];
        float2 v0 = unpack2(accp[rr][0]), v1 = unpack2(accp[rr][1]);
        float2 v2 = unpack2(accp[rr][2]), v3 = unpack2(accp[rr][3]);
        float y[8];
        y[0] = fmaxf(v0.x, 0.f); y[1] = fmaxf(v0.y, 0.f);
        y[2] = fmaxf(v1.x, 0.f); y[3] = fmaxf(v1.y, 0.f);
        y[4] = fmaxf(v2.x, 0.f); y[5] = fmaxf(v2.y, 0.f);
        y[6] = fmaxf(v3.x, 0.f); y[7] = fmaxf(v3.y, 0.f);
        *(float4*)(g_edge + (size_t)e * D + j0)     = make_float4(y[0], y[1], y[2], y[3]);
        *(float4*)(g_edge + (size_t)e * D + j0 + 4) = make_float4(y[4], y[5], y[6], y[7]);
        float* pb = g_ebar + (size_t)d * D + j0;
        red_add_v4(pb,     y[0], y[1], y[2], y[3]);
        red_add_v4(pb + 4, y[4], y[5], y[6], y[7]);
    }
}

// ---------------- node update (fused NP): relu(node@Wn1 + ebar@Wn2 + uprojN) -
__global__ void k_node(const float* __restrict__ Nsrc,
                       const int* __restrict__ batch,
                       const float* __restrict__ Wn_w)
{
    extern __shared__ float sm[];
    float* As = sm;
    float* Ws = sm + D * AS_LD;
    float* inv_s = Ws + D * D;
    int* b_s = (int*)(inv_s + 64);

    int row0 = blockIdx.x * 64;
    int t = threadIdx.x;
    if (t < 64) {
        int row = row0 + t;
        if (row < NN) { inv_s[t] = 1.f / fmaxf(g_indeg[row], 1.f); b_s[t] = batch[row]; }
        else          { inv_s[t] = 0.f; b_s[t] = 0; }
    }
    __syncthreads();

    // ---- phase 1: ebar (normalized) @ Wn2, with per-graph ebar sums ----
    {
        const float4* W4 = (const float4*)(Wn_w + D * D);   // Wn2 rows 128..255
        float4* Ws4 = (float4*)Ws;
#pragma unroll
        for (int i = 0; i < 32; i++) Ws4[t + i * 128] = W4[t + i * 128];
#pragma unroll
        for (int i = 0; i < 16; i++) {
            int idx = t + i * 128;
            int r = idx >> 5, kq = idx & 31;
            int row = row0 + r;
            float4 v = make_float4(0.f, 0.f, 0.f, 0.f);
            if (row < NN) {
                v = *(const float4*)(g_ebar + (size_t)row * D + kq * 4);
                float sc = inv_s[r];
                v.x *= sc; v.y *= sc; v.z *= sc; v.w *= sc;
                red_add_v4(g_gsum_ebar + (size_t)b_s[r] * D + kq * 4, v.x, v.y, v.z, v.w);
            }
            As[(kq * 4 + 0) * AS_LD + r] = v.x;
            As[(kq * 4 + 1) * AS_LD + r] = v.y;
            As[(kq * 4 + 2) * AS_LD + r] = v.z;
            As[(kq * 4 + 3) * AS_LD + r] = v.w;
        }
    }
    __syncthreads();

    int j0 = (t & 15) * 8, r0 = (t >> 4) * 8;
    unsigned long long accp[8][4];
#pragma unroll
    for (int rr = 0; rr < 8; rr++) {
        const float* pu = g_uprojN + (size_t)b_s[r0 + rr] * D + j0;
        float4 u0 = *(const float4*)pu, u1 = *(const float4*)(pu + 4);
        accp[rr][0] = pack2(u0.x, u0.y);
        accp[rr][1] = pack2(u0.z, u0.w);
        accp[rr][2] = pack2(u1.x, u1.y);
        accp[rr][3] = pack2(u1.z, u1.w);
    }
    mm_accum(As, Ws, r0, j0, accp);
    __syncthreads();   // all reads of As/Ws done before reload

    // ---- phase 2: node @ Wn1, accumulate into same accp ----
    {
        const float4* W4 = (const float4*)Wn_w;             // Wn1 rows 0..127
        float4* Ws4 = (float4*)Ws;
#pragma unroll
        for (int i = 0; i < 32; i++) Ws4[t + i * 128] = W4[t + i * 128];
#pragma unroll
        for (int i = 0; i < 16; i++) {
            int idx = t + i * 128;
            int r = idx >> 5, kq = idx & 31;
            int row = row0 + r; if (row >= NN) row = NN - 1;
            float4 v = *(const float4*)(Nsrc + (size_t)row * D + kq * 4);
            As[(kq * 4 + 0) * AS_LD + r] = v.x;
            As[(kq * 4 + 1) * AS_LD + r] = v.y;
            As[(kq * 4 + 2) * AS_LD + r] = v.z;
            As[(kq * 4 + 3) * AS_LD + r] = v.w;
        }
    }
    __syncthreads();
    mm_accum(As, Ws, r0, j0, accp);

#pragma unroll
    for (int rr = 0; rr < 8; rr++) {
        int row = row0 + r0 + rr;
        if (row < NN) {
            int gb = b_s[r0 + rr];
            float2 v0 = unpack2(accp[rr][0]), v1 = unpack2(accp[rr][1]);
            float2 v2 = unpack2(accp[rr][2]), v3 = unpack2(accp[rr][3]);
            float y[8];
            y[0] = fmaxf(v0.x, 0.f); y[1] = fmaxf(v0.y, 0.f);
            y[2] = fmaxf(v1.x, 0.f); y[3] = fmaxf(v1.y, 0.f);
            y[4] = fmaxf(v2.x, 0.f); y[5] = fmaxf(v2.y, 0.f);
            y[6] = fmaxf(v3.x, 0.f); y[7] = fmaxf(v3.y, 0.f);
            *(float4*)(g_node + (size_t)row * D + j0)     = make_float4(y[0], y[1], y[2], y[3]);
            *(float4*)(g_node + (size_t)row * D + j0 + 4) = make_float4(y[4], y[5], y[6], y[7]);
            float* pg = g_gsum_node + (size_t)gb * D + j0;
            red_add_v4(pg,     y[0], y[1], y[2], y[3]);
            red_add_v4(pg + 4, y[4], y[5], y[6], y[7]);
        }
    }
}

// ---------------- global update + next-pass u projections --------------------
__global__ void k_global(const float* __restrict__ Wg_w, const float* __restrict__ Wg_b,
                         const float* __restrict__ We_w, const float* __restrict__ We_b,
                         const float* __restrict__ Wn_w, const float* __restrict__ Wn_b)
{
    int g = blockIdx.x, j = threadIdx.x;
    __shared__ float nm[D], em[D], uu[D], un[D];
    float inv = 1.f / fmaxf(g_cntg[g], 1.f);
    nm[j] = g_gsum_node[g * D + j] * inv;
    em[j] = g_gsum_ebar[g * D + j] * inv;
    uu[j] = g_u[g * D + j];
    __syncthreads();
    float acc = Wg_b[j];
#pragma unroll 4
    for (int k = 0; k < D; k++) {
        acc = fmaf(nm[k], Wg_w[k * D + j], acc);
        acc = fmaf(em[k], Wg_w[(D + k) * D + j], acc);
        acc = fmaf(uu[k], Wg_w[(2 * D + k) * D + j], acc);
    }
    float r = fmaxf(acc, 0.f);
    g_u[g * D + j] = r;
    un[j] = r;
    __syncthreads();
    float aE = We_b[j], aN = Wn_b[j];
#pragma unroll 4
    for (int k = 0; k < D; k++) {
        float uv = un[k];
        aE = fmaf(uv, We_w[(3 * D + k) * D + j], aE);
        aN = fmaf(uv, Wn_w[(2 * D + k) * D + j], aN);
    }
    g_uprojE[g * D + j] = aE;
    g_uprojN[g * D + j] = aN;
}

// ---------------- readout ----------------------------------------------------
__global__ void k_readout(const float* __restrict__ lin_w, const float* __restrict__ lin_b,
                          float* __restrict__ out)
{
    int g = blockIdx.x, t = threadIdx.x;
    __shared__ float pooled[3 * D];
    float inv = 1.f / fmaxf(g_cntg[g], 1.f);
    pooled[t]         = g_gsum_node[g * D + t] * inv;
    pooled[D + t]     = g_gsum_ebar[g * D + t] * inv;
    pooled[2 * D + t] = g_u[g * D + t];
    __syncthreads();
    if (t < NCLS) {
        float acc = lin_b[t];
#pragma unroll 4
        for (int k = 0; k < 3 * D; k++) acc = fmaf(pooled[k], lin_w[k * NCLS + t], acc);
        out[g * NCLS + t] = acc;
    }
}

// ---------------- host launcher ----------------------------------------------
extern "C" void kernel_launch(void* const* d_in, const int* in_sizes, int n_in,
                              void* d_out, int out_size)
{
    const float* node_in = (const float*)d_in[0];
    const float* edge_in = (const float*)d_in[1];
    const float* u_in    = (const float*)d_in[2];
    const int*   ei      = (const int*)d_in[3];
    const int*   batch   = (const int*)d_in[4];
    const float* We_w = (const float*)d_in[5];
    const float* We_b = (const float*)d_in[6];
    const float* Wn_w = (const float*)d_in[7];
    const float* Wn_b = (const float*)d_in[8];
    const float* Wg_w = (const float*)d_in[9];
    const float* Wg_b = (const float*)d_in[10];
    const float* lin_w = (const float*)d_in[11];
    const float* lin_b = (const float*)d_in[12];
    float* out = (float*)d_out;

    float *p_NW = nullptr, *p_node = nullptr, *p_edge = nullptr;
    cudaGetSymbolAddress((void**)&p_NW,   g_NW);
    cudaGetSymbolAddress((void**)&p_node, g_node);
    cudaGetSymbolAddress((void**)&p_edge, g_edge);

    const int SMEM_GEMM = (D * AS_LD + D * D) * 4;
    const int SMEM_EDGE = SMEM_GEMM + 3 * 64 * 4;
    const int SMEM_NODE = SMEM_GEMM + 2 * 64 * 4;
    cudaFuncSetAttribute(k_gemm_proj, cudaFuncAttributeMaxDynamicSharedMemorySize, SMEM_GEMM);
    cudaFuncSetAttribute(k_edge,      cudaFuncAttributeMaxDynamicSharedMemorySize, SMEM_EDGE);
    cudaFuncSetAttribute(k_node,      cudaFuncAttributeMaxDynamicSharedMemorySize, SMEM_NODE);

    k_init<<<(NN + 255) / 256, 256>>>(u_in);
    k_hist<<<(NE + 255) / 256, 256>>>(ei, batch);
    k_uproj<<<NG, D>>>(We_w, We_b, Wn_w, Wn_b);

    const float* nsrc = node_in;
    const float* esrc = edge_in;
    int nrb = (NN + 63) / 64;
    for (int p = 0; p < 3; p++) {
        k_zero_pass<<<1024, 256>>>();
        // NW1|NW2 = node @ [We1|We2]
        k_gemm_proj<<<dim3(nrb, 2), 128, SMEM_GEMM>>>(nsrc, We_w, We_w + D * D, p_NW, 2 * D, NN);
        // edge update + scatter into per-dst sums
        k_edge<<<NE / 64, 128, SMEM_EDGE>>>(esrc, We_w, ei, batch);
        // node update (fused NP GEMM) + per-graph sums
        k_node<<<nrb, 128, SMEM_NODE>>>(nsrc, batch, Wn_w);
        // global update + u projections for next pass
        k_global<<<NG, D>>>(Wg_w, Wg_b, We_w, We_b, Wn_w, Wn_b);
        nsrc = p_node;
        esrc = p_edge;
    }
    k_readout<<<NG, D>>>(lin_w, lin_b, out);
}